// round 10
// baseline (speedup 1.0000x reference)
#include <cuda_runtime.h>
#include <cuda_fp16.h>
#include <cuda_fp4.h>

// MXFP4 (E2M1) block fake-quant embedding gather — R10:
//   - redux.sync.max.u32 for the 8-lane |x| max (1 op vs 3 serial SHFLs;
//     valid since |x| bit patterns of nonneg floats are order-isomorphic)
//   - int4-vectorized index loads (4 LDG instead of 16)
//   - TOK_CTA=16 single wave, st.global.cs streaming stores, HW E2M1 cvt
// Model: at the DRAM write-direction wall (~67MB output @ ~3.9 TB/s);
// this round only trims issue/latency fringe.
// d_in[0]: int32 indices, 16384 tokens
// d_in[1]: float32 embedding table, (50257, 1024)
// d_out  : float32 (16384, 1024)

#define F        1024
#define TOK_CTA  16

__device__ __forceinline__ float2 fp4_pair(float x, float y, float inv) {
    float2 a = make_float2(x * inv, y * inv);
    __nv_fp4x2_storage_t p =
        __nv_cvt_float2_to_fp4x2(a, __NV_E2M1, cudaRoundNearest);
    __half2_raw hr = __nv_cvt_fp4x2_to_halfraw2(p, __NV_E2M1);
    __half2 h = *reinterpret_cast<__half2*>(&hr);
    return __half22float2(h);                      // exact grid values
}

__global__ void __launch_bounds__(256)
mxfp4_embed_kernel(const int* __restrict__ idx,
                   const float* __restrict__ emb,
                   float* __restrict__ out) {
    const int t = threadIdx.x;                      // one float4 of a row
    const int base = blockIdx.x * TOK_CTA;
    const int lane = t & 31;
    // 8-lane group mask for redux (group g = lanes [8g, 8g+8))
    const unsigned gmask = 0xFFu << (lane & ~7);

    // vectorized uniform index loads (L1 broadcast)
    int rows[TOK_CTA];
    #pragma unroll
    for (int j = 0; j < TOK_CTA / 4; j++) {
        int4 r4 = __ldg(reinterpret_cast<const int4*>(idx + base) + j);
        rows[j * 4 + 0] = r4.x;
        rows[j * 4 + 1] = r4.y;
        rows[j * 4 + 2] = r4.z;
        rows[j * 4 + 3] = r4.w;
    }

    float4* dst = reinterpret_cast<float4*>(out) + (size_t)base * (F / 4) + t;

    #pragma unroll
    for (int j = 0; j < TOK_CTA; j++) {
        float4 v = __ldg(reinterpret_cast<const float4*>(emb) +
                         (size_t)rows[j] * (F / 4) + t);

        // max |.| over this thread's 4 values (as nonneg-float bit pattern)
        float ml = fmaxf(fmaxf(fabsf(v.x), fabsf(v.y)),
                         fmaxf(fabsf(v.z), fabsf(v.w)));
        // one-shot 8-lane group max: u32 max == float max for nonneg floats
        unsigned mb = __float_as_uint(ml);
        asm("redux.sync.max.u32 %0, %1, %2;" : "=r"(mb) : "r"(mb), "r"(gmask));
        const float m = __uint_as_float(mb);

        const float sc  = (m == 0.0f) ? 1.0f : m * (1.0f / 6.0f);
        const float inv = (m == 0.0f) ? 0.0f : __fdividef(6.0f, m);

        float2 g0 = fp4_pair(v.x, v.y, inv);
        float2 g1 = fp4_pair(v.z, v.w, inv);

        float4 r;
        r.x = g0.x * sc;
        r.y = g0.y * sc;
        r.z = g1.x * sc;
        r.w = g1.y * sc;

        // streaming store: evict-first, clean writeback drain
        __stcs(dst + (size_t)j * (F / 4), r);
    }
}

extern "C" void kernel_launch(void* const* d_in, const int* in_sizes, int n_in,
                              void* d_out, int out_size) {
    const int*   idx = (const int*)d_in[0];
    const float* emb = (const float*)d_in[1];
    float*       out = (float*)d_out;

    const int tokens = in_sizes[0];              // 16384
    mxfp4_embed_kernel<<<tokens / TOK_CTA, 256>>>(idx, emb, out);
}

// round 11
// speedup vs baseline: 1.6922x; 1.6922x over previous
#include <cuda_runtime.h>
#include <cuda_fp16.h>
#include <cuda_fp4.h>

// MXFP4 (E2M1) block fake-quant embedding gather — R11:
//   = R9 (best: 17.15us) + int4-vectorized index loads only.
//   R10 post-mortem: redux.sync with 4 distinct masks per warp serializes
//   (29us regression) — reverted to the 3x shfl.xor width=8 chain.
// Model: at the HBM write-direction wall (~67MB output @ ~3.9 TB/s).
// d_in[0]: int32 indices, 16384 tokens
// d_in[1]: float32 embedding table, (50257, 1024)
// d_out  : float32 (16384, 1024)

#define F        1024
#define TOK_CTA  16

__device__ __forceinline__ float2 fp4_pair(float x, float y, float inv) {
    float2 a = make_float2(x * inv, y * inv);
    __nv_fp4x2_storage_t p =
        __nv_cvt_float2_to_fp4x2(a, __NV_E2M1, cudaRoundNearest);
    __half2_raw hr = __nv_cvt_fp4x2_to_halfraw2(p, __NV_E2M1);
    __half2 h = *reinterpret_cast<__half2*>(&hr);
    return __half22float2(h);                      // exact grid values
}

__global__ void __launch_bounds__(256)
mxfp4_embed_kernel(const int* __restrict__ idx,
                   const float* __restrict__ emb,
                   float* __restrict__ out) {
    const int t = threadIdx.x;                      // one float4 of a row
    const int base = blockIdx.x * TOK_CTA;

    // vectorized uniform index loads (L1 broadcast): 4x LDG.128
    int rows[TOK_CTA];
    #pragma unroll
    for (int j = 0; j < TOK_CTA / 4; j++) {
        int4 r4 = __ldg(reinterpret_cast<const int4*>(idx + base) + j);
        rows[j * 4 + 0] = r4.x;
        rows[j * 4 + 1] = r4.y;
        rows[j * 4 + 2] = r4.z;
        rows[j * 4 + 3] = r4.w;
    }

    float4* dst = reinterpret_cast<float4*>(out) + (size_t)base * (F / 4) + t;

    #pragma unroll
    for (int j = 0; j < TOK_CTA; j++) {
        float4 v = __ldg(reinterpret_cast<const float4*>(emb) +
                         (size_t)rows[j] * (F / 4) + t);

        float m = fmaxf(fmaxf(fabsf(v.x), fabsf(v.y)),
                        fmaxf(fabsf(v.z), fabsf(v.w)));
        #pragma unroll
        for (int o = 4; o > 0; o >>= 1)
            m = fmaxf(m, __shfl_xor_sync(0xFFFFFFFFu, m, o, 8));

        const float sc  = (m == 0.0f) ? 1.0f : m * (1.0f / 6.0f);
        const float inv = (m == 0.0f) ? 0.0f : __fdividef(6.0f, m);

        float2 g0 = fp4_pair(v.x, v.y, inv);
        float2 g1 = fp4_pair(v.z, v.w, inv);

        float4 r;
        r.x = g0.x * sc;
        r.y = g0.y * sc;
        r.z = g1.x * sc;
        r.w = g1.y * sc;

        // streaming store: evict-first, clean writeback drain
        __stcs(dst + (size_t)j * (F / 4), r);
    }
}

extern "C" void kernel_launch(void* const* d_in, const int* in_sizes, int n_in,
                              void* d_out, int out_size) {
    const int*   idx = (const int*)d_in[0];
    const float* emb = (const float*)d_in[1];
    float*       out = (float*)d_out;

    const int tokens = in_sizes[0];              // 16384
    mxfp4_embed_kernel<<<tokens / TOK_CTA, 256>>>(idx, emb, out);
}